// round 2
// baseline (speedup 1.0000x reference)
#include <cuda_runtime.h>
#include <math.h>

// Problem constants
#define B_   2
#define S_   2048
#define D_   2048
#define NH_  16
#define HD_  128
#define M_   (B_*S_)          // 4096 total rows

// ---------------------------------------------------------------------------
// Scratch (static device globals — no runtime allocation allowed)
// ---------------------------------------------------------------------------
__device__ float g_q[(size_t)M_ * D_];
__device__ float g_k[(size_t)M_ * D_];
__device__ float g_v[(size_t)M_ * D_];
__device__ float g_attn[(size_t)M_ * D_];

// ---------------------------------------------------------------------------
// GEMM (TN): C[m, n] = sum_d A[m, d] * W[n, d]
//   A: [4096, 2048] row-major, W: [2048, 2048] row-major, C: [4096, 2048]
// Optional fused RoPE epilogue (for Q and K projections).
// Block: 128x128 tile, K-tile 16, 256 threads, 8x8 per-thread microtile.
// ---------------------------------------------------------------------------
__global__ __launch_bounds__(256) void gemm_tn_rope(
    const float* __restrict__ A, const float* __restrict__ W,
    float* __restrict__ C, const float* __restrict__ fc, int applyRope)
{
    __shared__ __align__(16) float As[16][132];
    __shared__ __align__(16) float Bs[16][132];

    const int tid = threadIdx.x;
    const int bm  = blockIdx.x * 128;
    const int bn  = blockIdx.y * 128;
    const int tx  = tid & 15;       // 0..15 -> columns
    const int ty  = tid >> 4;       // 0..15 -> rows
    const int lrow = tid >> 2;      // 0..63 (load row)
    const int lk4  = (tid & 3) << 2; // 0,4,8,12 (load k quad)

    float acc[8][8];
    #pragma unroll
    for (int i = 0; i < 8; i++)
        #pragma unroll
        for (int j = 0; j < 8; j++) acc[i][j] = 0.f;

    for (int kt = 0; kt < D_; kt += 16) {
        #pragma unroll
        for (int half = 0; half < 2; half++) {
            int r = lrow + half * 64;
            float4 va = *(const float4*)(A + (size_t)(bm + r) * D_ + kt + lk4);
            As[lk4+0][r] = va.x; As[lk4+1][r] = va.y;
            As[lk4+2][r] = va.z; As[lk4+3][r] = va.w;
            float4 vb = *(const float4*)(W + (size_t)(bn + r) * D_ + kt + lk4);
            Bs[lk4+0][r] = vb.x; Bs[lk4+1][r] = vb.y;
            Bs[lk4+2][r] = vb.z; Bs[lk4+3][r] = vb.w;
        }
        __syncthreads();

        #pragma unroll
        for (int k = 0; k < 16; k++) {
            float a[8], b[8];
            *(float4*)&a[0] = *(const float4*)&As[k][ty*4];
            *(float4*)&a[4] = *(const float4*)&As[k][ty*4 + 64];
            *(float4*)&b[0] = *(const float4*)&Bs[k][tx*4];
            *(float4*)&b[4] = *(const float4*)&Bs[k][tx*4 + 64];
            #pragma unroll
            for (int i = 0; i < 8; i++)
                #pragma unroll
                for (int j = 0; j < 8; j++)
                    acc[i][j] += a[i] * b[j];
        }
        __syncthreads();
    }

    // Epilogue: optional RoPE, then vectorized store.
    #pragma unroll
    for (int ih = 0; ih < 2; ih++) {
        #pragma unroll
        for (int ii = 0; ii < 4; ii++) {
            int i = ih * 4 + ii;
            int r = ty * 4 + ii + ih * 64;
            int m = bm + r;
            int s = m & (S_ - 1);
            #pragma unroll
            for (int jh = 0; jh < 2; jh++) {
                int c0 = tx * 4 + jh * 64;
                int e  = bn + c0;
                float v0 = acc[i][jh*4+0], v1 = acc[i][jh*4+1];
                float v2 = acc[i][jh*4+2], v3 = acc[i][jh*4+3];
                if (applyRope) {
                    // pairs (v0,v1) and (v2,v3): e is 4-aligned so pairs line up
                    int d0 = e & (HD_ - 1);
                    int j0 = d0 >> 1;
                    float c_  = fc[s * HD_ + j0*2 + 0];
                    float sn_ = fc[s * HD_ + j0*2 + 1];
                    float r0 = v0 * c_  - v1 * sn_;
                    float i0 = v0 * sn_ + v1 * c_;
                    float c1  = fc[s * HD_ + (j0+1)*2 + 0];
                    float s1_ = fc[s * HD_ + (j0+1)*2 + 1];
                    float r1 = v2 * c1  - v3 * s1_;
                    float i1 = v2 * s1_ + v3 * c1;
                    v0 = r0; v1 = i0; v2 = r1; v3 = i1;
                }
                float4 o4 = make_float4(v0, v1, v2, v3);
                *(float4*)(C + (size_t)m * D_ + e) = o4;
            }
        }
    }
}

// ---------------------------------------------------------------------------
// Flash attention (causal), fp32.
// Grid: (S/64, NH, B). 128 threads = (ty 0..15 rows-of-4) x (tx 0..7 cols-of-8).
// Per block: Q tile 64x128 resident; loop over K/V tiles of 64 rows.
// ---------------------------------------------------------------------------
#define QK_STRIDE 129
#define V_STRIDE  132
#define P_STRIDE  65
#define ATT_SMEM_FLOATS (64*QK_STRIDE*2 + 64*V_STRIDE + 64*P_STRIDE)
#define ATT_SMEM_BYTES  (ATT_SMEM_FLOATS * 4)

__global__ __launch_bounds__(128) void attention_kernel(
    const float* __restrict__ Q, const float* __restrict__ K,
    const float* __restrict__ V, float* __restrict__ O)
{
    extern __shared__ float sm[];
    float* Qs = sm;                       // 64 x 129
    float* Ks = Qs + 64*QK_STRIDE;        // 64 x 129
    float* Vs = Ks + 64*QK_STRIDE;        // 64 x 132 (float4-friendly)
    float* Ps = Vs + 64*V_STRIDE;         // 64 x 65

    const int b  = blockIdx.z;
    const int h  = blockIdx.y;
    const int qi = blockIdx.x;
    const int tid = threadIdx.x;
    const int tx = tid & 7;               // 0..7  -> 8 score cols / 16 out cols
    const int ty = tid >> 3;              // 0..15 -> 4 rows

    const size_t base = ((size_t)b * S_ * NH_ + h) * HD_;
    const size_t rowstride = (size_t)NH_ * HD_;   // 2048

    // Load Q tile (64 rows x 128)
    for (int idx = tid; idx < 64*32; idx += 128) {
        int r  = idx >> 5;
        int c4 = (idx & 31) << 2;
        float4 v = *(const float4*)(Q + base + (size_t)(qi*64 + r) * rowstride + c4);
        Qs[r*QK_STRIDE + c4+0] = v.x; Qs[r*QK_STRIDE + c4+1] = v.y;
        Qs[r*QK_STRIDE + c4+2] = v.z; Qs[r*QK_STRIDE + c4+3] = v.w;
    }

    float m_i[4], l_i[4], o[4][16];
    #pragma unroll
    for (int i = 0; i < 4; i++) {
        m_i[i] = -1e30f; l_i[i] = 0.f;
        #pragma unroll
        for (int c = 0; c < 16; c++) o[i][c] = 0.f;
    }

    const float scale = 0.08838834764831845f;  // 1/sqrt(128)

    for (int kt = 0; kt <= qi; kt++) {
        __syncthreads();   // K/V/P from previous iter fully consumed
        // Load K and V tiles (64 x 128 each)
        for (int idx = tid; idx < 64*32; idx += 128) {
            int r  = idx >> 5;
            int c4 = (idx & 31) << 2;
            size_t g = base + (size_t)(kt*64 + r) * rowstride + c4;
            float4 vk = *(const float4*)(K + g);
            Ks[r*QK_STRIDE + c4+0] = vk.x; Ks[r*QK_STRIDE + c4+1] = vk.y;
            Ks[r*QK_STRIDE + c4+2] = vk.z; Ks[r*QK_STRIDE + c4+3] = vk.w;
            float4 vv = *(const float4*)(V + g);
            *(float4*)&Vs[r*V_STRIDE + c4] = vv;
        }
        __syncthreads();

        // S = Q K^T (4x8 chunk per thread)
        float sacc[4][8];
        #pragma unroll
        for (int i = 0; i < 4; i++)
            #pragma unroll
            for (int j = 0; j < 8; j++) sacc[i][j] = 0.f;

        #pragma unroll 8
        for (int d = 0; d < HD_; d++) {
            float qv[4], kv[8];
            #pragma unroll
            for (int i = 0; i < 4; i++) qv[i] = Qs[(ty*4 + i)*QK_STRIDE + d];
            #pragma unroll
            for (int j = 0; j < 8; j++) kv[j] = Ks[(tx*8 + j)*QK_STRIDE + d];
            #pragma unroll
            for (int i = 0; i < 4; i++)
                #pragma unroll
                for (int j = 0; j < 8; j++)
                    sacc[i][j] += qv[i] * kv[j];
        }

        const bool diag = (kt == qi);
        #pragma unroll
        for (int i = 0; i < 4; i++) {
            int qrow = qi*64 + ty*4 + i;
            #pragma unroll
            for (int j = 0; j < 8; j++) {
                float sv = sacc[i][j] * scale;
                if (diag && (kt*64 + tx*8 + j) > qrow) sv = -1e30f;
                sacc[i][j] = sv;
            }
            // row max across 8 local + 8 lanes (tx = lane&7)
            float mloc = sacc[i][0];
            #pragma unroll
            for (int j = 1; j < 8; j++) mloc = fmaxf(mloc, sacc[i][j]);
            mloc = fmaxf(mloc, __shfl_xor_sync(0xffffffffu, mloc, 1));
            mloc = fmaxf(mloc, __shfl_xor_sync(0xffffffffu, mloc, 2));
            mloc = fmaxf(mloc, __shfl_xor_sync(0xffffffffu, mloc, 4));
            float mnew = fmaxf(m_i[i], mloc);
            float corr = __expf(m_i[i] - mnew);
            float lsum = 0.f;
            #pragma unroll
            for (int j = 0; j < 8; j++) {
                float p = __expf(sacc[i][j] - mnew);
                sacc[i][j] = p;
                lsum += p;
            }
            lsum += __shfl_xor_sync(0xffffffffu, lsum, 1);
            lsum += __shfl_xor_sync(0xffffffffu, lsum, 2);
            lsum += __shfl_xor_sync(0xffffffffu, lsum, 4);
            l_i[i] = l_i[i] * corr + lsum;
            m_i[i] = mnew;
            #pragma unroll
            for (int c = 0; c < 16; c++) o[i][c] *= corr;
            #pragma unroll
            for (int j = 0; j < 8; j++)
                Ps[(ty*4 + i)*P_STRIDE + tx*8 + j] = sacc[i][j];
        }
        __syncthreads();

        // O += P V  (rows ty*4.., cols tx*16..)
        #pragma unroll 2
        for (int k = 0; k < 64; k++) {
            float p0 = Ps[(ty*4 + 0)*P_STRIDE + k];
            float p1 = Ps[(ty*4 + 1)*P_STRIDE + k];
            float p2 = Ps[(ty*4 + 2)*P_STRIDE + k];
            float p3 = Ps[(ty*4 + 3)*P_STRIDE + k];
            const float* vrow = &Vs[k*V_STRIDE + tx*16];
            #pragma unroll
            for (int c4 = 0; c4 < 4; c4++) {
                float4 v = *(const float4*)(vrow + c4*4);
                o[0][c4*4+0] += p0*v.x; o[0][c4*4+1] += p0*v.y;
                o[0][c4*4+2] += p0*v.z; o[0][c4*4+3] += p0*v.w;
                o[1][c4*4+0] += p1*v.x; o[1][c4*4+1] += p1*v.y;
                o[1][c4*4+2] += p1*v.z; o[1][c4*4+3] += p1*v.w;
                o[2][c4*4+0] += p2*v.x; o[2][c4*4+1] += p2*v.y;
                o[2][c4*4+2] += p2*v.z; o[2][c4*4+3] += p2*v.w;
                o[3][c4*4+0] += p3*v.x; o[3][c4*4+1] += p3*v.y;
                o[3][c4*4+2] += p3*v.z; o[3][c4*4+3] += p3*v.w;
            }
        }
    }

    // Normalize and store
    #pragma unroll
    for (int i = 0; i < 4; i++) {
        float inv = 1.0f / l_i[i];
        int srow = qi*64 + ty*4 + i;
        size_t g = base + (size_t)srow * rowstride + tx*16;
        #pragma unroll
        for (int c4 = 0; c4 < 4; c4++) {
            float4 v = make_float4(o[i][c4*4+0]*inv, o[i][c4*4+1]*inv,
                                   o[i][c4*4+2]*inv, o[i][c4*4+3]*inv);
            *(float4*)(O + g + c4*4) = v;
        }
    }
}

// ---------------------------------------------------------------------------
// Launch
// Inputs (metadata order): x, start_pos, freqs_cis, mask, wq, wk, wv, wo
// ---------------------------------------------------------------------------
extern "C" void kernel_launch(void* const* d_in, const int* in_sizes, int n_in,
                              void* d_out, int out_size) {
    (void)in_sizes; (void)n_in; (void)out_size;
    const float* x  = (const float*)d_in[0];
    const float* fc = (const float*)d_in[2];
    const float* wq = (const float*)d_in[4];
    const float* wk = (const float*)d_in[5];
    const float* wv = (const float*)d_in[6];
    const float* wo = (const float*)d_in[7];
    float* out = (float*)d_out;

    float *q, *k, *v, *attn;
    cudaGetSymbolAddress((void**)&q,    g_q);
    cudaGetSymbolAddress((void**)&k,    g_k);
    cudaGetSymbolAddress((void**)&v,    g_v);
    cudaGetSymbolAddress((void**)&attn, g_attn);

    cudaFuncSetAttribute(attention_kernel,
                         cudaFuncAttributeMaxDynamicSharedMemorySize,
                         ATT_SMEM_BYTES);

    dim3 gemm_grid(M_/128, D_/128);   // (32, 16)
    gemm_tn_rope<<<gemm_grid, 256>>>(x, wq, q, fc, 1);
    gemm_tn_rope<<<gemm_grid, 256>>>(x, wk, k, fc, 1);
    gemm_tn_rope<<<gemm_grid, 256>>>(x, wv, v, fc, 0);

    dim3 att_grid(S_/64, NH_, B_);    // (32, 16, 2)
    attention_kernel<<<att_grid, 128, ATT_SMEM_BYTES>>>(q, k, v, attn);

    gemm_tn_rope<<<gemm_grid, 256>>>(attn, wo, out, fc, 0);
}